// round 1
// baseline (speedup 1.0000x reference)
#include <cuda_runtime.h>
#include <math.h>

#define NN 100000
#define HID 128
#define RR 8
#define LL 2
#define HH 4
#define DD 32
#define EE 625000

// ---------------- scratch (device globals; no allocation) ----------------
__device__ float    g_h[(size_t)NN * HID];          // node features
__device__ float    g_kqv[(size_t)NN * 3 * HID];    // fused k|q|v per layer
__device__ float    g_alpha[(size_t)EE * HH];       // logits, then exp() in-place
__device__ unsigned g_amax[(size_t)NN * HH];        // encoded float max
__device__ float    g_denom[(size_t)NN * HH];
__device__ float    g_aggr[(size_t)NN * HID];

// monotonic uint encoding of float for atomicMax over signed values
__device__ __forceinline__ unsigned fenc(float f) {
    unsigned u = __float_as_uint(f);
    return (u & 0x80000000u) ? ~u : (u | 0x80000000u);
}
__device__ __forceinline__ float fdec(unsigned k) {
    return (k & 0x80000000u) ? __uint_as_float(k & 0x7fffffffu) : __uint_as_float(~k);
}
#define ENC_NEG_INF 0x007fffffu   // fenc(-inf)

// ---------------- kernels ----------------

// h = emb[x]
__global__ void gather_kernel(const float* __restrict__ emb, const int* __restrict__ x) {
    size_t i = (size_t)blockIdx.x * blockDim.x + threadIdx.x;
    if (i >= (size_t)NN * HID) return;
    int node = (int)(i >> 7);
    int c = (int)(i & 127);
    g_h[i] = emb[(size_t)x[node] * HID + c];
}

// zero aggr, reset amax/denom
__global__ void init_layer_kernel() {
    size_t i = (size_t)blockIdx.x * blockDim.x + threadIdx.x;
    if (i >= (size_t)NN * HID) return;
    g_aggr[i] = 0.f;
    if (i < (size_t)NN * HH) {
        g_amax[i] = ENC_NEG_INF;
        g_denom[i] = 0.f;
    }
}

// kqv = h @ W_kqv[l] + b  : M=NN, K=128, Ncols=384. 64-row tiles, full W in smem.
#define TILE_M 64
__global__ __launch_bounds__(256) void kqv_gemm_kernel(const float* __restrict__ W,
                                                       const float* __restrict__ bias) {
    extern __shared__ float sm[];
    float* Ws = sm;                   // 128*384
    float* As = sm + 128 * 384;       // 64*129 (padded)
    int tid = threadIdx.x;
    int row0 = blockIdx.x * TILE_M;

    const float4* W4 = (const float4*)W;
    float4* Ws4 = (float4*)Ws;
    for (int i = tid; i < 128 * 384 / 4; i += 256) Ws4[i] = W4[i];
    for (int i = tid; i < TILE_M * 32; i += 256) {
        int row = i >> 5, c4 = i & 31;
        int gr = row0 + row;
        float4 v = (gr < NN) ? ((const float4*)(g_h + (size_t)gr * 128))[c4]
                             : make_float4(0.f, 0.f, 0.f, 0.f);
        float* d = As + row * 129 + c4 * 4;
        d[0] = v.x; d[1] = v.y; d[2] = v.z; d[3] = v.w;
    }
    __syncthreads();

    int nl = tid & 63;
    int cg = tid >> 6;         // 0..3
    int grow = row0 + nl;
    for (int chunk = 0; chunk < 3; chunk++) {
        int col0 = chunk * 128 + cg * 32;
        float acc[32];
#pragma unroll
        for (int c = 0; c < 32; c++) acc[c] = 0.f;
        for (int k = 0; k < 128; k++) {
            float a = As[nl * 129 + k];
            const float4* wrow = (const float4*)(Ws + k * 384 + col0);
#pragma unroll
            for (int c4 = 0; c4 < 8; c4++) {
                float4 w = wrow[c4];
                acc[c4 * 4 + 0] = fmaf(a, w.x, acc[c4 * 4 + 0]);
                acc[c4 * 4 + 1] = fmaf(a, w.y, acc[c4 * 4 + 1]);
                acc[c4 * 4 + 2] = fmaf(a, w.z, acc[c4 * 4 + 2]);
                acc[c4 * 4 + 3] = fmaf(a, w.w, acc[c4 * 4 + 3]);
            }
        }
        if (grow < NN) {
            float* o = g_kqv + (size_t)grow * 384 + col0;
#pragma unroll
            for (int c = 0; c < 32; c++) o[c] = acc[c] + bias[col0 + c];
        }
    }
}

// pass1: warp per edge; k-transform per head, attention logit, segment max
__global__ __launch_bounds__(256) void edge_pass1_kernel(const int* __restrict__ ei,
                                                         const int* __restrict__ et,
                                                         const float* __restrict__ Wk,
                                                         const float* __restrict__ pr) {
    int e = (blockIdx.x * blockDim.x + threadIdx.x) >> 5;
    int lane = threadIdx.x & 31;
    if (e >= EE) return;
    int src = ei[e];
    int dst = ei[EE + e];
    int r = et[e];
    const float* kbase = g_kqv + (size_t)src * 384;
    const float* qbase = g_kqv + (size_t)dst * 384 + 128;
    float kh[4], qh[4];
#pragma unroll
    for (int h = 0; h < 4; h++) {
        kh[h] = kbase[h * 32 + lane];
        qh[h] = qbase[h * 32 + lane];
    }
    const float* Wr = Wk + (size_t)r * HH * DD * DD;
#pragma unroll
    for (int h = 0; h < 4; h++) {
        const float* Wh = Wr + h * 1024 + lane;
        float kp = 0.f;
#pragma unroll
        for (int d = 0; d < 32; d++)
            kp = fmaf(__shfl_sync(0xffffffffu, kh[h], d), Wh[d * 32], kp);
        float p = qh[h] * kp;
#pragma unroll
        for (int o = 16; o > 0; o >>= 1) p += __shfl_xor_sync(0xffffffffu, p, o);
        if (lane == 0) {
            float a = p * pr[r * HH + h] * 0.17677669529663689f; // 1/sqrt(32)
            g_alpha[(size_t)e * 4 + h] = a;
            atomicMax(&g_amax[(size_t)dst * 4 + h], fenc(a));
        }
    }
}

// pass2: ee = exp(alpha - max), denom accumulation
__global__ void edge_pass2_kernel(const int* __restrict__ ei) {
    size_t i = (size_t)blockIdx.x * blockDim.x + threadIdx.x;
    if (i >= (size_t)EE * HH) return;
    int e = (int)(i >> 2);
    int h = (int)(i & 3);
    int dst = ei[EE + e];
    float m = fdec(g_amax[(size_t)dst * 4 + h]);
    float ee = expf(g_alpha[i] - m);
    g_alpha[i] = ee;
    atomicAdd(&g_denom[(size_t)dst * 4 + h], ee);
}

// pass3: warp per edge; v-transform per head, weighted scatter into aggr
__global__ __launch_bounds__(256) void edge_pass3_kernel(const int* __restrict__ ei,
                                                         const int* __restrict__ et,
                                                         const float* __restrict__ Wv) {
    int e = (blockIdx.x * blockDim.x + threadIdx.x) >> 5;
    int lane = threadIdx.x & 31;
    if (e >= EE) return;
    int src = ei[e];
    int dst = ei[EE + e];
    int r = et[e];
    const float* vbase = g_kqv + (size_t)src * 384 + 256;
    float vh[4], wgt[4];
#pragma unroll
    for (int h = 0; h < 4; h++) {
        vh[h] = vbase[h * 32 + lane];
        wgt[h] = g_alpha[(size_t)e * 4 + h] / g_denom[(size_t)dst * 4 + h];
    }
    const float* Wr = Wv + (size_t)r * HH * DD * DD;
#pragma unroll
    for (int h = 0; h < 4; h++) {
        const float* Wh = Wr + h * 1024 + lane;
        float vp = 0.f;
#pragma unroll
        for (int d = 0; d < 32; d++)
            vp = fmaf(__shfl_sync(0xffffffffu, vh[h], d), Wh[d * 32], vp);
        atomicAdd(&g_aggr[(size_t)dst * 128 + h * 32 + lane], vp * wgt[h]);
    }
}

// out: o = gelu(aggr) @ W_out + b; h = relu(sg*o + (1-sg)*h)
__global__ __launch_bounds__(256) void out_gemm_kernel(const float* __restrict__ W,
                                                       const float* __restrict__ bias,
                                                       const float* __restrict__ skip,
                                                       int l, float* __restrict__ out2) {
    extern __shared__ float sm[];
    float* Ws = sm;                // 128*128
    float* As = sm + 128 * 128;    // 64*129
    int tid = threadIdx.x;
    int row0 = blockIdx.x * TILE_M;

    const float4* W4 = (const float4*)W;
    float4* Ws4 = (float4*)Ws;
    for (int i = tid; i < 128 * 128 / 4; i += 256) Ws4[i] = W4[i];
    for (int i = tid; i < TILE_M * 32; i += 256) {
        int row = i >> 5, c4 = i & 31;
        int gr = row0 + row;
        float4 v = (gr < NN) ? ((const float4*)(g_aggr + (size_t)gr * 128))[c4]
                             : make_float4(0.f, 0.f, 0.f, 0.f);
        float* d = As + row * 129 + c4 * 4;
        // exact gelu
        d[0] = 0.5f * v.x * (1.f + erff(v.x * 0.70710678118654752f));
        d[1] = 0.5f * v.y * (1.f + erff(v.y * 0.70710678118654752f));
        d[2] = 0.5f * v.z * (1.f + erff(v.z * 0.70710678118654752f));
        d[3] = 0.5f * v.w * (1.f + erff(v.w * 0.70710678118654752f));
    }
    __syncthreads();

    int nl = tid & 63;
    int cg = tid >> 6;
    int grow = row0 + nl;
    int col0 = cg * 32;
    float acc[32];
#pragma unroll
    for (int c = 0; c < 32; c++) acc[c] = 0.f;
    for (int k = 0; k < 128; k++) {
        float a = As[nl * 129 + k];
        const float4* wrow = (const float4*)(Ws + k * 128 + col0);
#pragma unroll
        for (int c4 = 0; c4 < 8; c4++) {
            float4 w = wrow[c4];
            acc[c4 * 4 + 0] = fmaf(a, w.x, acc[c4 * 4 + 0]);
            acc[c4 * 4 + 1] = fmaf(a, w.y, acc[c4 * 4 + 1]);
            acc[c4 * 4 + 2] = fmaf(a, w.z, acc[c4 * 4 + 2]);
            acc[c4 * 4 + 3] = fmaf(a, w.w, acc[c4 * 4 + 3]);
        }
    }
    if (grow < NN) {
        float sg = 1.f / (1.f + expf(-skip[l]));
        float* hrow = g_h + (size_t)grow * 128 + col0;
#pragma unroll
        for (int c = 0; c < 32; c++) {
            float o = acc[c] + bias[col0 + c];
            float hn = fmaxf(sg * o + (1.f - sg) * hrow[c], 0.f);
            hrow[c] = hn;
            if (out2) out2[(size_t)grow * 128 + col0 + c] = hn;
        }
    }
}

// ---------------- host ----------------
extern "C" void kernel_launch(void* const* d_in, const int* in_sizes, int n_in,
                              void* d_out, int out_size) {
    const float* emb   = (const float*)d_in[0];
    const float* W_kqv = (const float*)d_in[1];
    const float* b_kqv = (const float*)d_in[2];
    const float* Wk    = (const float*)d_in[3];
    const float* Wv    = (const float*)d_in[4];
    const float* p_rel = (const float*)d_in[5];
    const float* W_out = (const float*)d_in[6];
    const float* b_out = (const float*)d_in[7];
    const float* skip  = (const float*)d_in[8];
    const int*   x     = (const int*)d_in[9];
    const int*   ei    = (const int*)d_in[10];
    const int*   et    = (const int*)d_in[11];
    float* out = (float*)d_out;

    const int SMEM_KQV = (128 * 384 + 64 * 129) * 4;  // 229632
    const int SMEM_OUT = (128 * 128 + 64 * 129) * 4;  // 98560
    cudaFuncSetAttribute(kqv_gemm_kernel, cudaFuncAttributeMaxDynamicSharedMemorySize, SMEM_KQV);
    cudaFuncSetAttribute(out_gemm_kernel, cudaFuncAttributeMaxDynamicSharedMemorySize, SMEM_OUT);

    const int nblocks_nh = (NN * HID + 255) / 256;     // 50000
    const int nblocks_m  = (NN + TILE_M - 1) / TILE_M; // 1563
    const int nblocks_e  = (EE + 7) / 8;               // 78125 (8 warps/block)
    const int nblocks_eh = (EE * HH + 255) / 256;

    gather_kernel<<<nblocks_nh, 256>>>(emb, x);

    for (int l = 0; l < LL; l++) {
        const float* Wkqv_l = W_kqv + (size_t)l * HID * 3 * HID;
        const float* bkqv_l = b_kqv + (size_t)l * 3 * HID;
        const float* Wk_l   = Wk + (size_t)l * RR * HH * DD * DD;
        const float* Wv_l   = Wv + (size_t)l * RR * HH * DD * DD;
        const float* pr_l   = p_rel + (size_t)l * RR * HH;
        const float* Wout_l = W_out + (size_t)l * HID * HID;
        const float* bout_l = b_out + (size_t)l * HID;

        kqv_gemm_kernel<<<nblocks_m, 256, SMEM_KQV>>>(Wkqv_l, bkqv_l);
        init_layer_kernel<<<nblocks_nh, 256>>>();
        edge_pass1_kernel<<<nblocks_e, 256>>>(ei, et, Wk_l, pr_l);
        edge_pass2_kernel<<<nblocks_eh, 256>>>(ei);
        edge_pass3_kernel<<<nblocks_e, 256>>>(ei, et, Wv_l);
        out_gemm_kernel<<<nblocks_m, 256, SMEM_OUT>>>(Wout_l, bout_l, skip, l,
                                                      (l == LL - 1) ? out : nullptr);
    }
}

// round 2
// speedup vs baseline: 1.0641x; 1.0641x over previous
#include <cuda_runtime.h>
#include <math.h>

#define NN 100000
#define HID 128
#define RR 8
#define LL 2
#define HH 4
#define DD 32
#define EE 625000
#define NB 98              // ceil(NN/1024)

// ---------------- scratch (device globals; no allocation) ----------------
__device__ float g_h[(size_t)NN * HID];
__device__ float g_kqv[(size_t)NN * 3 * HID];
__device__ float g_aggr[(size_t)NN * HID];
__device__ float g_Qp[(size_t)NN * RR * HID];   // Wk[r] @ q[n]  (index d)
__device__ float g_Vp[(size_t)NN * RR * HID];   // v[n] @ Wv[r]  (index f)
__device__ int   g_deg[NN];
__device__ int   g_cur[NN];
__device__ int   g_off[NN + 1];
__device__ int   g_bsum[NB];
__device__ int   g_esrc[EE];
__device__ int   g_erel[EE];

// ---------------- gather ----------------
__global__ void gather_kernel(const float* __restrict__ emb, const int* __restrict__ x) {
    size_t i = (size_t)blockIdx.x * blockDim.x + threadIdx.x;
    if (i >= (size_t)NN * HID) return;
    int node = (int)(i >> 7);
    int c = (int)(i & 127);
    g_h[i] = emb[(size_t)x[node] * HID + c];
}

// ---------------- sort edges by dst (counting sort -> CSR) ----------------
__global__ void zero_deg_kernel() {
    int i = blockIdx.x * blockDim.x + threadIdx.x;
    if (i < NN) g_deg[i] = 0;
}
__global__ void hist_kernel(const int* __restrict__ ei) {
    int e = blockIdx.x * blockDim.x + threadIdx.x;
    if (e < EE) atomicAdd(&g_deg[ei[EE + e]], 1);
}
__global__ __launch_bounds__(1024) void scan1_kernel() {
    __shared__ int s[1024];
    int i = blockIdx.x * 1024 + threadIdx.x;
    int v = (i < NN) ? g_deg[i] : 0;
    s[threadIdx.x] = v;
    __syncthreads();
    for (int off = 1; off < 1024; off <<= 1) {
        int t = (threadIdx.x >= off) ? s[threadIdx.x - off] : 0;
        __syncthreads();
        s[threadIdx.x] += t;
        __syncthreads();
    }
    if (i < NN) g_off[i] = s[threadIdx.x] - v;   // block-local exclusive
    if (threadIdx.x == 1023) g_bsum[blockIdx.x] = s[1023];
}
__global__ __launch_bounds__(128) void scan2_kernel() {
    __shared__ int s[128];
    int v = (threadIdx.x < NB) ? g_bsum[threadIdx.x] : 0;
    s[threadIdx.x] = v;
    __syncthreads();
    for (int off = 1; off < 128; off <<= 1) {
        int t = (threadIdx.x >= off) ? s[threadIdx.x - off] : 0;
        __syncthreads();
        s[threadIdx.x] += t;
        __syncthreads();
    }
    if (threadIdx.x < NB) g_bsum[threadIdx.x] = s[threadIdx.x] - v;  // exclusive
}
__global__ void scan3_kernel() {
    int i = blockIdx.x * blockDim.x + threadIdx.x;
    if (i < NN) {
        g_off[i] += g_bsum[i >> 10];
        g_cur[i] = 0;
    }
    if (i == 0) g_off[NN] = EE;
}
__global__ void scatter_kernel(const int* __restrict__ ei, const int* __restrict__ et) {
    int e = blockIdx.x * blockDim.x + threadIdx.x;
    if (e >= EE) return;
    int dst = ei[EE + e];
    int pos = g_off[dst] + atomicAdd(&g_cur[dst], 1);
    g_esrc[pos] = ei[e];
    g_erel[pos] = et[e];
}

// ---------------- kqv = h @ W_kqv + b ----------------
#define TILE_M 64
__global__ __launch_bounds__(256) void kqv_gemm_kernel(const float* __restrict__ W,
                                                       const float* __restrict__ bias) {
    extern __shared__ float sm[];
    float* Ws = sm;                   // 128*384
    float* As = sm + 128 * 384;       // 64*129
    int tid = threadIdx.x;
    int row0 = blockIdx.x * TILE_M;

    const float4* W4 = (const float4*)W;
    float4* Ws4 = (float4*)Ws;
    for (int i = tid; i < 128 * 384 / 4; i += 256) Ws4[i] = W4[i];
    for (int i = tid; i < TILE_M * 32; i += 256) {
        int row = i >> 5, c4 = i & 31;
        int gr = row0 + row;
        float4 v = (gr < NN) ? ((const float4*)(g_h + (size_t)gr * 128))[c4]
                             : make_float4(0.f, 0.f, 0.f, 0.f);
        float* d = As + row * 129 + c4 * 4;
        d[0] = v.x; d[1] = v.y; d[2] = v.z; d[3] = v.w;
    }
    __syncthreads();

    int nl = tid & 63;
    int cg = tid >> 6;
    int grow = row0 + nl;
    for (int chunk = 0; chunk < 3; chunk++) {
        int col0 = chunk * 128 + cg * 32;
        float acc[32];
#pragma unroll
        for (int c = 0; c < 32; c++) acc[c] = 0.f;
        for (int k = 0; k < 128; k++) {
            float a = As[nl * 129 + k];
            const float4* wrow = (const float4*)(Ws + k * 384 + col0);
#pragma unroll
            for (int c4 = 0; c4 < 8; c4++) {
                float4 w = wrow[c4];
                acc[c4 * 4 + 0] = fmaf(a, w.x, acc[c4 * 4 + 0]);
                acc[c4 * 4 + 1] = fmaf(a, w.y, acc[c4 * 4 + 1]);
                acc[c4 * 4 + 2] = fmaf(a, w.z, acc[c4 * 4 + 2]);
                acc[c4 * 4 + 3] = fmaf(a, w.w, acc[c4 * 4 + 3]);
            }
        }
        if (grow < NN) {
            float* o = g_kqv + (size_t)grow * 384 + col0;
#pragma unroll
            for (int c = 0; c < 32; c++) o[c] = acc[c] + bias[col0 + c];
        }
    }
}

// ---------------- precompute Qp[n,r] = Wk[r]·q[n], Vp[n,r] = v[n]·Wv[r] ----------------
// grid: (node_tiles, R). block 256 = 64 nodes x 4 heads.
__global__ __launch_bounds__(256) void prep_kernel(const float* __restrict__ Wk,
                                                   const float* __restrict__ Wv) {
    extern __shared__ float sm[];
    float* qs  = sm;                  // 64*129
    float* vs  = sm + 64 * 129;       // 64*129
    float* wkT = vs + 64 * 129;       // 4096 : [h][f][d] = Wk[r,h,d,f]
    float* wvv = wkT + 4096;          // 4096 : [h][d][f]
    int tid = threadIdx.x;
    int r = blockIdx.y;
    int row0 = blockIdx.x * 64;

    for (int i = tid; i < 64 * 32; i += 256) {
        int row = i >> 5, c4 = i & 31;
        int gr = row0 + row;
        float4 qv = (gr < NN) ? ((const float4*)(g_kqv + (size_t)gr * 384 + 128))[c4]
                              : make_float4(0.f, 0.f, 0.f, 0.f);
        float4 vv = (gr < NN) ? ((const float4*)(g_kqv + (size_t)gr * 384 + 256))[c4]
                              : make_float4(0.f, 0.f, 0.f, 0.f);
        float* dq = qs + row * 129 + c4 * 4;
        dq[0] = qv.x; dq[1] = qv.y; dq[2] = qv.z; dq[3] = qv.w;
        float* dv = vs + row * 129 + c4 * 4;
        dv[0] = vv.x; dv[1] = vv.y; dv[2] = vv.z; dv[3] = vv.w;
    }
    const float* WkR = Wk + (size_t)r * 4096;
    const float* WvR = Wv + (size_t)r * 4096;
    for (int i = tid; i < 4096; i += 256) {
        int h = i >> 10, rem = i & 1023, d = rem >> 5, f = rem & 31;
        wkT[h * 1024 + f * 32 + d] = WkR[i];
        wvv[i] = WvR[i];
    }
    __syncthreads();

    int nl = tid & 63;
    int h = tid >> 6;
    float accQ[32], accV[32];
#pragma unroll
    for (int c = 0; c < 32; c++) { accQ[c] = 0.f; accV[c] = 0.f; }
    const float* qrow = qs + nl * 129 + h * 32;
    const float* vrow = vs + nl * 129 + h * 32;
    for (int t = 0; t < 32; t++) {
        float a = qrow[t];   // q_f, f=t
        const float4* w4 = (const float4*)(wkT + h * 1024 + t * 32);
#pragma unroll
        for (int j = 0; j < 8; j++) {
            float4 w = w4[j];
            accQ[j * 4 + 0] = fmaf(a, w.x, accQ[j * 4 + 0]);
            accQ[j * 4 + 1] = fmaf(a, w.y, accQ[j * 4 + 1]);
            accQ[j * 4 + 2] = fmaf(a, w.z, accQ[j * 4 + 2]);
            accQ[j * 4 + 3] = fmaf(a, w.w, accQ[j * 4 + 3]);
        }
        float b = vrow[t];   // v_d, d=t
        const float4* x4 = (const float4*)(wvv + h * 1024 + t * 32);
#pragma unroll
        for (int j = 0; j < 8; j++) {
            float4 w = x4[j];
            accV[j * 4 + 0] = fmaf(b, w.x, accV[j * 4 + 0]);
            accV[j * 4 + 1] = fmaf(b, w.y, accV[j * 4 + 1]);
            accV[j * 4 + 2] = fmaf(b, w.z, accV[j * 4 + 2]);
            accV[j * 4 + 3] = fmaf(b, w.w, accV[j * 4 + 3]);
        }
    }
    int gr = row0 + nl;
    if (gr < NN) {
        float4* oq = (float4*)(g_Qp + (((size_t)gr * 8 + r) * 128) + h * 32);
        float4* ov = (float4*)(g_Vp + (((size_t)gr * 8 + r) * 128) + h * 32);
#pragma unroll
        for (int j = 0; j < 8; j++) {
            oq[j] = make_float4(accQ[j * 4], accQ[j * 4 + 1], accQ[j * 4 + 2], accQ[j * 4 + 3]);
            ov[j] = make_float4(accV[j * 4], accV[j * 4 + 1], accV[j * 4 + 2], accV[j * 4 + 3]);
        }
    }
}

// ---------------- fused attention: warp per dst node, online softmax ----------------
__device__ __forceinline__ void online_upd(float& m, float& den, float& acc,
                                           float s, float v) {
    float mn = fmaxf(m, s);
    float c = __expf(m - mn);
    float w = __expf(s - mn);
    den = den * c + w;
    acc = acc * c + w * v;
    m = mn;
}

__global__ __launch_bounds__(256) void attn_kernel(const float* __restrict__ pr) {
    __shared__ float prs[RR * HH];
    if (threadIdx.x < RR * HH) prs[threadIdx.x] = pr[threadIdx.x];
    __syncthreads();
    int n = (blockIdx.x * blockDim.x + threadIdx.x) >> 5;
    int lane = threadIdx.x & 31;
    if (n >= NN) return;
    int beg = g_off[n], end = g_off[n + 1];
    const float SCALE = 0.17677669529663689f;   // 1/sqrt(32)

    float m0 = -INFINITY, m1 = -INFINITY, m2 = -INFINITY, m3 = -INFINITY;
    float d0 = 0.f, d1 = 0.f, d2 = 0.f, d3 = 0.f;
    float a0 = 0.f, a1 = 0.f, a2 = 0.f, a3 = 0.f;

    for (int e = beg; e < end; e++) {
        int src = g_esrc[e];
        int r = g_erel[e];
        const float* kb = g_kqv + (size_t)src * 384;
        const float* qb = g_Qp + ((size_t)n * 8 + r) * 128;
        const float* vb = g_Vp + ((size_t)src * 8 + r) * 128;
        float p0 = kb[lane] * qb[lane];
        float p1 = kb[32 + lane] * qb[32 + lane];
        float p2 = kb[64 + lane] * qb[64 + lane];
        float p3 = kb[96 + lane] * qb[96 + lane];
        float v0 = vb[lane];
        float v1 = vb[32 + lane];
        float v2 = vb[64 + lane];
        float v3 = vb[96 + lane];
#pragma unroll
        for (int o = 16; o > 0; o >>= 1) {
            p0 += __shfl_xor_sync(0xffffffffu, p0, o);
            p1 += __shfl_xor_sync(0xffffffffu, p1, o);
            p2 += __shfl_xor_sync(0xffffffffu, p2, o);
            p3 += __shfl_xor_sync(0xffffffffu, p3, o);
        }
        const float* prr = prs + r * 4;
        online_upd(m0, d0, a0, p0 * prr[0] * SCALE, v0);
        online_upd(m1, d1, a1, p1 * prr[1] * SCALE, v1);
        online_upd(m2, d2, a2, p2 * prr[2] * SCALE, v2);
        online_upd(m3, d3, a3, p3 * prr[3] * SCALE, v3);
    }
    float* o = g_aggr + (size_t)n * 128;
    o[lane]      = (d0 > 0.f) ? a0 / d0 : 0.f;
    o[32 + lane] = (d1 > 0.f) ? a1 / d1 : 0.f;
    o[64 + lane] = (d2 > 0.f) ? a2 / d2 : 0.f;
    o[96 + lane] = (d3 > 0.f) ? a3 / d3 : 0.f;
}

// ---------------- out: o = gelu(aggr) @ W_out + b; h = relu(sg*o + (1-sg)*h) ----------------
__global__ __launch_bounds__(256) void out_gemm_kernel(const float* __restrict__ W,
                                                       const float* __restrict__ bias,
                                                       const float* __restrict__ skip,
                                                       int l, float* __restrict__ out2) {
    extern __shared__ float sm[];
    float* Ws = sm;                // 128*128
    float* As = sm + 128 * 128;    // 64*129
    int tid = threadIdx.x;
    int row0 = blockIdx.x * TILE_M;

    const float4* W4 = (const float4*)W;
    float4* Ws4 = (float4*)Ws;
    for (int i = tid; i < 128 * 128 / 4; i += 256) Ws4[i] = W4[i];
    for (int i = tid; i < TILE_M * 32; i += 256) {
        int row = i >> 5, c4 = i & 31;
        int gr = row0 + row;
        float4 v = (gr < NN) ? ((const float4*)(g_aggr + (size_t)gr * 128))[c4]
                             : make_float4(0.f, 0.f, 0.f, 0.f);
        float* d = As + row * 129 + c4 * 4;
        d[0] = 0.5f * v.x * (1.f + erff(v.x * 0.70710678118654752f));
        d[1] = 0.5f * v.y * (1.f + erff(v.y * 0.70710678118654752f));
        d[2] = 0.5f * v.z * (1.f + erff(v.z * 0.70710678118654752f));
        d[3] = 0.5f * v.w * (1.f + erff(v.w * 0.70710678118654752f));
    }
    __syncthreads();

    int nl = tid & 63;
    int cg = tid >> 6;
    int grow = row0 + nl;
    int col0 = cg * 32;
    float acc[32];
#pragma unroll
    for (int c = 0; c < 32; c++) acc[c] = 0.f;
    for (int k = 0; k < 128; k++) {
        float a = As[nl * 129 + k];
        const float4* wrow = (const float4*)(Ws + k * 128 + col0);
#pragma unroll
        for (int c4 = 0; c4 < 8; c4++) {
            float4 w = wrow[c4];
            acc[c4 * 4 + 0] = fmaf(a, w.x, acc[c4 * 4 + 0]);
            acc[c4 * 4 + 1] = fmaf(a, w.y, acc[c4 * 4 + 1]);
            acc[c4 * 4 + 2] = fmaf(a, w.z, acc[c4 * 4 + 2]);
            acc[c4 * 4 + 3] = fmaf(a, w.w, acc[c4 * 4 + 3]);
        }
    }
    if (grow < NN) {
        float sg = 1.f / (1.f + expf(-skip[l]));
        float* hrow = g_h + (size_t)grow * 128 + col0;
#pragma unroll
        for (int c = 0; c < 32; c++) {
            float o = acc[c] + bias[col0 + c];
            float hn = fmaxf(sg * o + (1.f - sg) * hrow[c], 0.f);
            hrow[c] = hn;
            if (out2) out2[(size_t)grow * 128 + col0 + c] = hn;
        }
    }
}

// ---------------- host ----------------
extern "C" void kernel_launch(void* const* d_in, const int* in_sizes, int n_in,
                              void* d_out, int out_size) {
    const float* emb   = (const float*)d_in[0];
    const float* W_kqv = (const float*)d_in[1];
    const float* b_kqv = (const float*)d_in[2];
    const float* Wk    = (const float*)d_in[3];
    const float* Wv    = (const float*)d_in[4];
    const float* p_rel = (const float*)d_in[5];
    const float* W_out = (const float*)d_in[6];
    const float* b_out = (const float*)d_in[7];
    const float* skip  = (const float*)d_in[8];
    const int*   x     = (const int*)d_in[9];
    const int*   ei    = (const int*)d_in[10];
    const int*   et    = (const int*)d_in[11];
    float* out = (float*)d_out;

    const int SMEM_KQV  = (128 * 384 + 64 * 129) * 4;      // 229632
    const int SMEM_OUT  = (128 * 128 + 64 * 129) * 4;      // 98560
    const int SMEM_PREP = (64 * 129 * 2 + 8192) * 4;       // 98816
    static bool attr_set = false;
    if (!attr_set) {
        cudaFuncSetAttribute(kqv_gemm_kernel, cudaFuncAttributeMaxDynamicSharedMemorySize, SMEM_KQV);
        cudaFuncSetAttribute(out_gemm_kernel, cudaFuncAttributeMaxDynamicSharedMemorySize, SMEM_OUT);
        cudaFuncSetAttribute(prep_kernel, cudaFuncAttributeMaxDynamicSharedMemorySize, SMEM_PREP);
        attr_set = true;
    }

    const int nblocks_nh = (NN * HID + 255) / 256;
    const int nblocks_m  = (NN + TILE_M - 1) / TILE_M;     // 1563
    const int nblocks_e  = (EE + 255) / 256;
    const int nblocks_n  = (NN + 255) / 256;
    const int nblocks_w  = (NN * 32 + 255) / 256;          // warp per node

    gather_kernel<<<nblocks_nh, 256>>>(emb, x);

    // ---- sort edges by dst into CSR ----
    zero_deg_kernel<<<nblocks_n, 256>>>();
    hist_kernel<<<nblocks_e, 256>>>(ei);
    scan1_kernel<<<NB, 1024>>>();
    scan2_kernel<<<1, 128>>>();
    scan3_kernel<<<nblocks_n, 256>>>();
    scatter_kernel<<<nblocks_e, 256>>>(ei, et);

    for (int l = 0; l < LL; l++) {
        const float* Wkqv_l = W_kqv + (size_t)l * HID * 3 * HID;
        const float* bkqv_l = b_kqv + (size_t)l * 3 * HID;
        const float* Wk_l   = Wk + (size_t)l * RR * HH * DD * DD;
        const float* Wv_l   = Wv + (size_t)l * RR * HH * DD * DD;
        const float* pr_l   = p_rel + (size_t)l * RR * HH;
        const float* Wout_l = W_out + (size_t)l * HID * HID;
        const float* bout_l = b_out + (size_t)l * HID;

        kqv_gemm_kernel<<<nblocks_m, 256, SMEM_KQV>>>(Wkqv_l, bkqv_l);
        dim3 pg(nblocks_m, RR);
        prep_kernel<<<pg, 256, SMEM_PREP>>>(Wk_l, Wv_l);
        attn_kernel<<<nblocks_w, 256>>>(pr_l);
        out_gemm_kernel<<<nblocks_m, 256, SMEM_OUT>>>(Wout_l, bout_l, skip, l,
                                                      (l == LL - 1) ? out : nullptr);
    }
}

// round 6
// speedup vs baseline: 1.1903x; 1.1186x over previous
#include <cuda_runtime.h>
#include <math.h>

#define NN 100000
#define HID 128
#define RR 8
#define LL 2
#define HH 4
#define DD 32
#define EE 625000
#define KB (NN * RR)            // 800000 sort buckets (dst*8 + rel)
#define NB2 782                 // ceil(KB/1024)

// ---------------- scratch (device globals; no allocation) ----------------
__device__ float g_h[(size_t)NN * HID];
__device__ float g_kqv[(size_t)NN * 3 * HID];
__device__ float g_aggr[(size_t)NN * HID];
__device__ float g_pm[(size_t)NN * HH];     // partial flash max   (pass 0)
__device__ float g_pd[(size_t)NN * HH];     // partial denom       (pass 0)
__device__ float g_po[(size_t)NN * HID];    // partial numerator   (pass 0)
__device__ int   g_deg[KB];
__device__ int   g_cur[KB];
__device__ int   g_off[KB + 1];
__device__ int   g_bsum[1024];
__device__ int   g_esrc[EE];

// ---------------- gather ----------------
__global__ void gather_kernel(const float* __restrict__ emb, const int* __restrict__ x) {
    size_t i = (size_t)blockIdx.x * blockDim.x + threadIdx.x;
    if (i >= (size_t)NN * HID) return;
    int node = (int)(i >> 7);
    int c = (int)(i & 127);
    g_h[i] = emb[(size_t)x[node] * HID + c];
}

// ---------------- counting sort by (dst, rel) -> CSR with 800K buckets ----------------
__global__ void zero_deg_kernel() {
    int i = blockIdx.x * blockDim.x + threadIdx.x;
    if (i < KB) g_deg[i] = 0;
}
__global__ void hist_kernel(const int* __restrict__ ei, const int* __restrict__ et) {
    int e = blockIdx.x * blockDim.x + threadIdx.x;
    if (e < EE) atomicAdd(&g_deg[ei[EE + e] * RR + et[e]], 1);
}
__global__ __launch_bounds__(1024) void scan1_kernel() {
    __shared__ int s[1024];
    int i = blockIdx.x * 1024 + threadIdx.x;
    int v = (i < KB) ? g_deg[i] : 0;
    s[threadIdx.x] = v;
    __syncthreads();
    for (int off = 1; off < 1024; off <<= 1) {
        int t = (threadIdx.x >= off) ? s[threadIdx.x - off] : 0;
        __syncthreads();
        s[threadIdx.x] += t;
        __syncthreads();
    }
    if (i < KB) g_off[i] = s[threadIdx.x] - v;
    if (threadIdx.x == 1023) g_bsum[blockIdx.x] = s[1023];
}
__global__ __launch_bounds__(1024) void scan2_kernel() {
    __shared__ int s[1024];
    int v = (threadIdx.x < NB2) ? g_bsum[threadIdx.x] : 0;
    s[threadIdx.x] = v;
    __syncthreads();
    for (int off = 1; off < 1024; off <<= 1) {
        int t = (threadIdx.x >= off) ? s[threadIdx.x - off] : 0;
        __syncthreads();
        s[threadIdx.x] += t;
        __syncthreads();
    }
    if (threadIdx.x < NB2) g_bsum[threadIdx.x] = s[threadIdx.x] - v;
}
__global__ void scan3_kernel() {
    int i = blockIdx.x * blockDim.x + threadIdx.x;
    if (i < KB) {
        g_off[i] += g_bsum[i >> 10];
        g_cur[i] = 0;
    }
    if (i == 0) g_off[KB] = EE;
}
__global__ void scatter_kernel(const int* __restrict__ ei, const int* __restrict__ et) {
    int e = blockIdx.x * blockDim.x + threadIdx.x;
    if (e >= EE) return;
    int key = ei[EE + e] * RR + et[e];
    int pos = g_off[key] + atomicAdd(&g_cur[key], 1);
    g_esrc[pos] = ei[e];
}

// ---------------- kqv = h @ W_kqv + b (W streamed in 128-col chunks) ----------------
#define TILE_M 64
__global__ __launch_bounds__(256) void kqv_gemm_kernel(const float* __restrict__ W,
                                                       const float* __restrict__ bias) {
    extern __shared__ float sm[];
    float* Ws = sm;                   // 128*128 (one chunk)
    float* As = sm + 128 * 128;       // 64*129
    int tid = threadIdx.x;
    int row0 = blockIdx.x * TILE_M;

    for (int i = tid; i < TILE_M * 32; i += 256) {
        int row = i >> 5, c4 = i & 31;
        int gr = row0 + row;
        float4 v = (gr < NN) ? ((const float4*)(g_h + (size_t)gr * 128))[c4]
                             : make_float4(0.f, 0.f, 0.f, 0.f);
        float* d = As + row * 129 + c4 * 4;
        d[0] = v.x; d[1] = v.y; d[2] = v.z; d[3] = v.w;
    }

    int nl = tid & 63;
    int cg = tid >> 6;
    int grow = row0 + nl;
    const float4* W4 = (const float4*)W;
    float4* Ws4 = (float4*)Ws;

    for (int chunk = 0; chunk < 3; chunk++) {
        __syncthreads();
        for (int i = tid; i < 128 * 32; i += 256) {
            int k = i >> 5, c4 = i & 31;
            Ws4[k * 32 + c4] = W4[k * 96 + chunk * 32 + c4];
        }
        __syncthreads();

        int col0 = cg * 32;
        float acc[32];
#pragma unroll
        for (int c = 0; c < 32; c++) acc[c] = 0.f;
        for (int k = 0; k < 128; k++) {
            float a = As[nl * 129 + k];
            const float4* wrow = (const float4*)(Ws + k * 128 + col0);
#pragma unroll
            for (int c4 = 0; c4 < 8; c4++) {
                float4 w = wrow[c4];
                acc[c4 * 4 + 0] = fmaf(a, w.x, acc[c4 * 4 + 0]);
                acc[c4 * 4 + 1] = fmaf(a, w.y, acc[c4 * 4 + 1]);
                acc[c4 * 4 + 2] = fmaf(a, w.z, acc[c4 * 4 + 2]);
                acc[c4 * 4 + 3] = fmaf(a, w.w, acc[c4 * 4 + 3]);
            }
        }
        if (grow < NN) {
            float* o = g_kqv + (size_t)grow * 384 + chunk * 128 + col0;
#pragma unroll
            for (int c = 0; c < 32; c++) o[c] = acc[c] + bias[chunk * 128 + col0 + c];
        }
    }
}

// ---------------- fused attention, two passes over relation halves ----------------
// Pass 0: relations [0,4): write unnormalized flash state (m, den, o) per node.
// Pass 1: relations [4,8): compute own state, merge pass-0 state, finalize.
// smem: WkT half [4rel][4head][f][d] transposed, WvS half [4rel][4head][d][f], prs[32].
#define ATTN_BLOCKS 148
#define HALF_FLOATS (4 * HH * DD * DD)   // 16384 per half
__global__ __launch_bounds__(512, 1) void attn_kernel(const float* __restrict__ Wk,
                                                      const float* __restrict__ Wv,
                                                      const float* __restrict__ pr,
                                                      int rbase, int phase) {
    extern __shared__ float sm[];
    float* WkT = sm;                   // 16384
    float* WvS = sm + HALF_FLOATS;     // 16384
    float* prs = WvS + HALF_FLOATS;    // 32
    int tid = threadIdx.x;

    const float4* Wv4 = (const float4*)(Wv + (size_t)rbase * 4096);
    float4* WvS4 = (float4*)WvS;
    for (int i = tid; i < HALF_FLOATS / 4; i += 512) WvS4[i] = Wv4[i];
    const float* WkH = Wk + (size_t)rbase * 4096;
    for (int i = tid; i < HALF_FLOATS; i += 512) {
        // i = ((rl*4+h)*32 + d)*32 + f  ->  WkT[((rl*4+h)*32 + f)*32 + d]
        int rh = i >> 10, rem = i & 1023, d = rem >> 5, f = rem & 31;
        WkT[(rh * 32 + f) * 32 + d] = WkH[i];
    }
    if (tid < 32) prs[tid] = pr[tid];
    __syncthreads();

    int lane = tid & 31;
    int warp = (blockIdx.x << 4) | (tid >> 5);
    const int nwarps = ATTN_BLOCKS * 16;
    const float SCALE = 0.17677669529663689f;   // 1/sqrt(32)
    const unsigned FULL = 0xffffffffu;

    for (int n = warp; n < NN; n += nwarps) {
        const float* qb = g_kqv + (size_t)n * 384 + 128;
        float q0 = qb[lane], q1 = qb[32 + lane], q2 = qb[64 + lane], q3 = qb[96 + lane];

        float m0 = -INFINITY, m1 = -INFINITY, m2 = -INFINITY, m3 = -INFINITY;
        float den0 = 0.f, den1 = 0.f, den2 = 0.f, den3 = 0.f;
        float o0 = 0.f, o1 = 0.f, o2 = 0.f, o3 = 0.f;

        int base = n * RR + rbase;
        for (int rl = 0; rl < 4; rl++) {
            int beg = g_off[base + rl];
            int end = g_off[base + rl + 1];
            if (beg == end) continue;

            // q~[h,d=lane] = sum_f WkT[rl,h,f,d] * q[h,f]
            float qt0 = 0.f, qt1 = 0.f, qt2 = 0.f, qt3 = 0.f;
            const float* wk0 = WkT + (rl * 4 + 0) * 1024;
            const float* wk1 = WkT + (rl * 4 + 1) * 1024;
            const float* wk2 = WkT + (rl * 4 + 2) * 1024;
            const float* wk3 = WkT + (rl * 4 + 3) * 1024;
#pragma unroll
            for (int f = 0; f < 32; f++) {
                qt0 = fmaf(__shfl_sync(FULL, q0, f), wk0[f * 32 + lane], qt0);
                qt1 = fmaf(__shfl_sync(FULL, q1, f), wk1[f * 32 + lane], qt1);
                qt2 = fmaf(__shfl_sync(FULL, q2, f), wk2[f * 32 + lane], qt2);
                qt3 = fmaf(__shfl_sync(FULL, q3, f), wk3[f * 32 + lane], qt3);
            }

            int rg = rbase + rl;
            float pr0 = prs[rg * 4 + 0] * SCALE, pr1 = prs[rg * 4 + 1] * SCALE;
            float pr2 = prs[rg * 4 + 2] * SCALE, pr3 = prs[rg * 4 + 3] * SCALE;

            float rm0 = -INFINITY, rm1 = -INFINITY, rm2 = -INFINITY, rm3 = -INFINITY;
            float rd0 = 0.f, rd1 = 0.f, rd2 = 0.f, rd3 = 0.f;
            float ra0 = 0.f, ra1 = 0.f, ra2 = 0.f, ra3 = 0.f;

            for (int e = beg; e < end; e++) {
                int src = g_esrc[e];
                const float* kb = g_kqv + (size_t)src * 384;
                float k0 = kb[lane], k1 = kb[32 + lane], k2 = kb[64 + lane], k3 = kb[96 + lane];
                float v0 = kb[256 + lane], v1 = kb[288 + lane], v2 = kb[320 + lane], v3 = kb[352 + lane];
                float p0 = k0 * qt0, p1 = k1 * qt1, p2 = k2 * qt2, p3 = k3 * qt3;
#pragma unroll
                for (int off = 16; off > 0; off >>= 1) {
                    p0 += __shfl_xor_sync(FULL, p0, off);
                    p1 += __shfl_xor_sync(FULL, p1, off);
                    p2 += __shfl_xor_sync(FULL, p2, off);
                    p3 += __shfl_xor_sync(FULL, p3, off);
                }
                float s0 = p0 * pr0, s1 = p1 * pr1, s2 = p2 * pr2, s3 = p3 * pr3;
                float nm, c, w;
                nm = fmaxf(rm0, s0); c = __expf(rm0 - nm); w = __expf(s0 - nm);
                rd0 = rd0 * c + w; ra0 = ra0 * c + w * v0; rm0 = nm;
                nm = fmaxf(rm1, s1); c = __expf(rm1 - nm); w = __expf(s1 - nm);
                rd1 = rd1 * c + w; ra1 = ra1 * c + w * v1; rm1 = nm;
                nm = fmaxf(rm2, s2); c = __expf(rm2 - nm); w = __expf(s2 - nm);
                rd2 = rd2 * c + w; ra2 = ra2 * c + w * v2; rm2 = nm;
                nm = fmaxf(rm3, s3); c = __expf(rm3 - nm); w = __expf(s3 - nm);
                rd3 = rd3 * c + w; ra3 = ra3 * c + w * v3; rm3 = nm;
            }

            // rv[h,f=lane] = sum_d ra[h,d] * WvS[rl,h,d,f]
            float rv0 = 0.f, rv1 = 0.f, rv2 = 0.f, rv3 = 0.f;
            const float* wv0 = WvS + (rl * 4 + 0) * 1024;
            const float* wv1 = WvS + (rl * 4 + 1) * 1024;
            const float* wv2 = WvS + (rl * 4 + 2) * 1024;
            const float* wv3 = WvS + (rl * 4 + 3) * 1024;
#pragma unroll
            for (int d = 0; d < 32; d++) {
                rv0 = fmaf(__shfl_sync(FULL, ra0, d), wv0[d * 32 + lane], rv0);
                rv1 = fmaf(__shfl_sync(FULL, ra1, d), wv1[d * 32 + lane], rv1);
                rv2 = fmaf(__shfl_sync(FULL, ra2, d), wv2[d * 32 + lane], rv2);
                rv3 = fmaf(__shfl_sync(FULL, ra3, d), wv3[d * 32 + lane], rv3);
            }

            // flash-merge run into node accumulators (rm finite here)
            float nm, c1, c2;
            nm = fmaxf(m0, rm0); c1 = __expf(m0 - nm); c2 = __expf(rm0 - nm);
            den0 = den0 * c1 + rd0 * c2; o0 = o0 * c1 + rv0 * c2; m0 = nm;
            nm = fmaxf(m1, rm1); c1 = __expf(m1 - nm); c2 = __expf(rm1 - nm);
            den1 = den1 * c1 + rd1 * c2; o1 = o1 * c1 + rv1 * c2; m1 = nm;
            nm = fmaxf(m2, rm2); c1 = __expf(m2 - nm); c2 = __expf(rm2 - nm);
            den2 = den2 * c1 + rd2 * c2; o2 = o2 * c1 + rv2 * c2; m2 = nm;
            nm = fmaxf(m3, rm3); c1 = __expf(m3 - nm); c2 = __expf(rm3 - nm);
            den3 = den3 * c1 + rd3 * c2; o3 = o3 * c1 + rv3 * c2; m3 = nm;
        }

        if (phase == 0) {
            if (lane == 0) {
                g_pm[(size_t)n * 4 + 0] = m0; g_pm[(size_t)n * 4 + 1] = m1;
                g_pm[(size_t)n * 4 + 2] = m2; g_pm[(size_t)n * 4 + 3] = m3;
                g_pd[(size_t)n * 4 + 0] = den0; g_pd[(size_t)n * 4 + 1] = den1;
                g_pd[(size_t)n * 4 + 2] = den2; g_pd[(size_t)n * 4 + 3] = den3;
            }
            float* po = g_po + (size_t)n * 128;
            po[lane] = o0; po[32 + lane] = o1; po[64 + lane] = o2; po[96 + lane] = o3;
        } else {
            // merge with pass-0 state (broadcast loads), finalize
            float am0 = g_pm[(size_t)n * 4 + 0], am1 = g_pm[(size_t)n * 4 + 1];
            float am2 = g_pm[(size_t)n * 4 + 2], am3 = g_pm[(size_t)n * 4 + 3];
            float ad0 = g_pd[(size_t)n * 4 + 0], ad1 = g_pd[(size_t)n * 4 + 1];
            float ad2 = g_pd[(size_t)n * 4 + 2], ad3 = g_pd[(size_t)n * 4 + 3];
            const float* po = g_po + (size_t)n * 128;
            float ao0 = po[lane], ao1 = po[32 + lane], ao2 = po[64 + lane], ao3 = po[96 + lane];
            float* og = g_aggr + (size_t)n * 128;

            float nm, ca, cb, den, num, res;
            nm = fmaxf(am0, m0); res = 0.f;
            if (nm > -INFINITY) {
                ca = __expf(am0 - nm); cb = __expf(m0 - nm);
                den = ad0 * ca + den0 * cb; num = ao0 * ca + o0 * cb;
                res = (den > 0.f) ? num / den : 0.f;
            }
            og[lane] = res;
            nm = fmaxf(am1, m1); res = 0.f;
            if (nm > -INFINITY) {
                ca = __expf(am1 - nm); cb = __expf(m1 - nm);
                den = ad1 * ca + den1 * cb; num = ao1 * ca + o1 * cb;
                res = (den > 0.f) ? num / den : 0.f;
            }
            og[32 + lane] = res;
            nm = fmaxf(am2, m2); res = 0.f;
            if (nm > -INFINITY) {
                ca = __expf(am2 - nm); cb = __expf(m2 - nm);
                den = ad2 * ca + den2 * cb; num = ao2 * ca + o2 * cb;
                res = (den > 0.f) ? num / den : 0.f;
            }
            og[64 + lane] = res;
            nm = fmaxf(am3, m3); res = 0.f;
            if (nm > -INFINITY) {
                ca = __expf(am3 - nm); cb = __expf(m3 - nm);
                den = ad3 * ca + den3 * cb; num = ao3 * ca + o3 * cb;
                res = (den > 0.f) ? num / den : 0.f;
            }
            og[96 + lane] = res;
        }
    }
}

// ---------------- out: o = gelu(aggr) @ W_out + b; h = relu(sg*o + (1-sg)*h) ----------------
__global__ __launch_bounds__(256) void out_gemm_kernel(const float* __restrict__ W,
                                                       const float* __restrict__ bias,
                                                       const float* __restrict__ skip,
                                                       int l, float* __restrict__ out2) {
    extern __shared__ float sm[];
    float* Ws = sm;                // 128*128
    float* As = sm + 128 * 128;    // 64*129
    int tid = threadIdx.x;
    int row0 = blockIdx.x * TILE_M;

    const float4* W4 = (const float4*)W;
    float4* Ws4 = (float4*)Ws;
    for (int i = tid; i < 128 * 128 / 4; i += 256) Ws4[i] = W4[i];
    for (int i = tid; i < TILE_M * 32; i += 256) {
        int row = i >> 5, c4 = i & 31;
        int gr = row0 + row;
        float4 v = (gr < NN) ? ((const float4*)(g_aggr + (size_t)gr * 128))[c4]
                             : make_float4(0.f, 0.f, 0.f, 0.f);
        float* d = As + row * 129 + c4 * 4;
        d[0] = 0.5f * v.x * (1.f + erff(v.x * 0.70710678118654752f));
        d[1] = 0.5f * v.y * (1.f + erff(v.y * 0.70710678118654752f));
        d[2] = 0.5f * v.z * (1.f + erff(v.z * 0.70710678118654752f));
        d[3] = 0.5f * v.w * (1.f + erff(v.w * 0.70710678118654752f));
    }
    __syncthreads();

    int nl = tid & 63;
    int cg = tid >> 6;
    int grow = row0 + nl;
    int col0 = cg * 32;
    float acc[32];
#pragma unroll
    for (int c = 0; c < 32; c++) acc[c] = 0.f;
    for (int k = 0; k < 128; k++) {
        float a = As[nl * 129 + k];
        const float4* wrow = (const float4*)(Ws + k * 128 + col0);
#pragma unroll
        for (int c4 = 0; c4 < 8; c4++) {
            float4 w = wrow[c4];
            acc[c4 * 4 + 0] = fmaf(a, w.x, acc[c4 * 4 + 0]);
            acc[c4 * 4 + 1] = fmaf(a, w.y, acc[c4 * 4 + 1]);
            acc[c4 * 4 + 2] = fmaf(a, w.z, acc[c4 * 4 + 2]);
            acc[c4 * 4 + 3] = fmaf(a, w.w, acc[c4 * 4 + 3]);
        }
    }
    if (grow < NN) {
        float sg = 1.f / (1.f + expf(-skip[l]));
        float* hrow = g_h + (size_t)grow * 128 + col0;
#pragma unroll
        for (int c = 0; c < 32; c++) {
            float o = acc[c] + bias[col0 + c];
            float hn = fmaxf(sg * o + (1.f - sg) * hrow[c], 0.f);
            hrow[c] = hn;
            if (out2) out2[(size_t)grow * 128 + col0 + c] = hn;
        }
    }
}

// ---------------- host ----------------
extern "C" void kernel_launch(void* const* d_in, const int* in_sizes, int n_in,
                              void* d_out, int out_size) {
    const float* emb   = (const float*)d_in[0];
    const float* W_kqv = (const float*)d_in[1];
    const float* b_kqv = (const float*)d_in[2];
    const float* Wk    = (const float*)d_in[3];
    const float* Wv    = (const float*)d_in[4];
    const float* p_rel = (const float*)d_in[5];
    const float* W_out = (const float*)d_in[6];
    const float* b_out = (const float*)d_in[7];
    const float* skip  = (const float*)d_in[8];
    const int*   x     = (const int*)d_in[9];
    const int*   ei    = (const int*)d_in[10];
    const int*   et    = (const int*)d_in[11];
    float* out = (float*)d_out;

    const int SMEM_GEMM = (128 * 128 + 64 * 129) * 4;        // 98560
    const int SMEM_ATTN = (HALF_FLOATS * 2 + 32) * 4;        // 131200
    static bool attr_set = false;
    if (!attr_set) {
        cudaFuncSetAttribute(kqv_gemm_kernel, cudaFuncAttributeMaxDynamicSharedMemorySize, SMEM_GEMM);
        cudaFuncSetAttribute(out_gemm_kernel, cudaFuncAttributeMaxDynamicSharedMemorySize, SMEM_GEMM);
        cudaFuncSetAttribute(attn_kernel, cudaFuncAttributeMaxDynamicSharedMemorySize, SMEM_ATTN);
        attr_set = true;
    }

    const int nblocks_nh = (NN * HID + 255) / 256;
    const int nblocks_m  = (NN + TILE_M - 1) / TILE_M;   // 1563
    const int nblocks_e  = (EE + 255) / 256;
    const int nblocks_kb = (KB + 255) / 256;
    const int nblocks_kb1 = (KB + 1 + 255) / 256;

    gather_kernel<<<nblocks_nh, 256>>>(emb, x);

    // sort edges by (dst, rel) into CSR
    zero_deg_kernel<<<nblocks_kb, 256>>>();
    hist_kernel<<<nblocks_e, 256>>>(ei, et);
    scan1_kernel<<<NB2, 1024>>>();
    scan2_kernel<<<1, 1024>>>();
    scan3_kernel<<<nblocks_kb1, 256>>>();
    scatter_kernel<<<nblocks_e, 256>>>(ei, et);

    for (int l = 0; l < LL; l++) {
        const float* Wkqv_l = W_kqv + (size_t)l * HID * 3 * HID;
        const float* bkqv_l = b_kqv + (size_t)l * 3 * HID;
        const float* Wk_l   = Wk + (size_t)l * RR * HH * DD * DD;
        const float* Wv_l   = Wv + (size_t)l * RR * HH * DD * DD;
        const float* pr_l   = p_rel + (size_t)l * RR * HH;
        const float* Wout_l = W_out + (size_t)l * HID * HID;
        const float* bout_l = b_out + (size_t)l * HID;

        kqv_gemm_kernel<<<nblocks_m, 256, SMEM_GEMM>>>(Wkqv_l, bkqv_l);
        attn_kernel<<<ATTN_BLOCKS, 512, SMEM_ATTN>>>(Wk_l, Wv_l, pr_l, 0, 0);
        attn_kernel<<<ATTN_BLOCKS, 512, SMEM_ATTN>>>(Wk_l, Wv_l, pr_l, 4, 1);
        out_gemm_kernel<<<nblocks_m, 256, SMEM_GEMM>>>(Wout_l, bout_l, skip, l,
                                                       (l == LL - 1) ? out : nullptr);
    }
}

// round 7
// speedup vs baseline: 1.2575x; 1.0564x over previous
#include <cuda_runtime.h>
#include <math.h>

#define NN 100000
#define HID 128
#define RR 8
#define LL 2
#define HH 4
#define DD 32
#define EE 625000
#define KB (NN * RR)            // 800000 sort buckets (dst*8 + rel)
#define NB2 782                 // ceil(KB/1024)

// ---------------- scratch (device globals; no allocation) ----------------
__device__ float g_h[(size_t)NN * HID];
__device__ float g_kqv[(size_t)NN * 3 * HID];
__device__ float g_aggr[(size_t)NN * HID];
__device__ float g_Qt[(size_t)KB * HID];    // q~ per nonempty run (indexed r*NN+idx)
__device__ float g_Vr[(size_t)KB * HID];    // raw v-sum, then transformed in place
__device__ float g_rm[(size_t)KB * HH];     // per-run flash max
__device__ float g_rd[(size_t)KB * HH];     // per-run denom
__device__ int   g_deg[KB];
__device__ int   g_cur[KB];
__device__ int   g_off[KB + 1];
__device__ int   g_bsum[1024];
__device__ int   g_esrc[EE];
__device__ int   g_runidx[KB];              // bucket -> run index (r*NN+idx) or -1
__device__ int   g_lnode[KB];               // run index -> node
__device__ int   g_lcnt[RR];

// ---------------- gather ----------------
__global__ void gather_kernel(const float* __restrict__ emb, const int* __restrict__ x) {
    size_t i = (size_t)blockIdx.x * blockDim.x + threadIdx.x;
    if (i >= (size_t)NN * HID) return;
    int node = (int)(i >> 7);
    int c = (int)(i & 127);
    g_h[i] = emb[(size_t)x[node] * HID + c];
}

// ---------------- counting sort by (dst, rel) -> CSR ----------------
__global__ void zero_deg_kernel() {
    int i = blockIdx.x * blockDim.x + threadIdx.x;
    if (i < KB) g_deg[i] = 0;
    if (i < RR) g_lcnt[i] = 0;
}
__global__ void hist_kernel(const int* __restrict__ ei, const int* __restrict__ et) {
    int e = blockIdx.x * blockDim.x + threadIdx.x;
    if (e < EE) atomicAdd(&g_deg[ei[EE + e] * RR + et[e]], 1);
}
__global__ __launch_bounds__(1024) void scan1_kernel() {
    __shared__ int s[1024];
    int i = blockIdx.x * 1024 + threadIdx.x;
    int v = (i < KB) ? g_deg[i] : 0;
    s[threadIdx.x] = v;
    __syncthreads();
    for (int off = 1; off < 1024; off <<= 1) {
        int t = (threadIdx.x >= off) ? s[threadIdx.x - off] : 0;
        __syncthreads();
        s[threadIdx.x] += t;
        __syncthreads();
    }
    if (i < KB) g_off[i] = s[threadIdx.x] - v;
    if (threadIdx.x == 1023) g_bsum[blockIdx.x] = s[1023];
}
__global__ __launch_bounds__(1024) void scan2_kernel() {
    __shared__ int s[1024];
    int v = (threadIdx.x < NB2) ? g_bsum[threadIdx.x] : 0;
    s[threadIdx.x] = v;
    __syncthreads();
    for (int off = 1; off < 1024; off <<= 1) {
        int t = (threadIdx.x >= off) ? s[threadIdx.x - off] : 0;
        __syncthreads();
        s[threadIdx.x] += t;
        __syncthreads();
    }
    if (threadIdx.x < NB2) g_bsum[threadIdx.x] = s[threadIdx.x] - v;
}
__global__ void scan3_kernel() {
    int i = blockIdx.x * blockDim.x + threadIdx.x;
    if (i < KB) {
        g_off[i] += g_bsum[i >> 10];
        g_cur[i] = 0;
    }
    if (i == 0) g_off[KB] = EE;
}
__global__ void scatter_kernel(const int* __restrict__ ei, const int* __restrict__ et) {
    int e = blockIdx.x * blockDim.x + threadIdx.x;
    if (e >= EE) return;
    int key = ei[EE + e] * RR + et[e];
    int pos = g_off[key] + atomicAdd(&g_cur[key], 1);
    g_esrc[pos] = ei[e];
}
__global__ void build_lists_kernel() {
    int b = blockIdx.x * blockDim.x + threadIdx.x;
    if (b >= KB) return;
    if (g_deg[b] > 0) {
        int r = b & 7;
        int n = b >> 3;
        int idx = atomicAdd(&g_lcnt[r], 1);
        g_runidx[b] = r * NN + idx;
        g_lnode[r * NN + idx] = n;
    } else {
        g_runidx[b] = -1;
    }
}

// ---------------- kqv = h @ W_kqv + b ----------------
#define TILE_M 64
__global__ __launch_bounds__(256) void kqv_gemm_kernel(const float* __restrict__ W,
                                                       const float* __restrict__ bias) {
    extern __shared__ float sm[];
    float* Ws = sm;                   // 128*128 (one chunk)
    float* As = sm + 128 * 128;       // 64*129
    int tid = threadIdx.x;
    int row0 = blockIdx.x * TILE_M;

    for (int i = tid; i < TILE_M * 32; i += 256) {
        int row = i >> 5, c4 = i & 31;
        int gr = row0 + row;
        float4 v = (gr < NN) ? ((const float4*)(g_h + (size_t)gr * 128))[c4]
                             : make_float4(0.f, 0.f, 0.f, 0.f);
        float* d = As + row * 129 + c4 * 4;
        d[0] = v.x; d[1] = v.y; d[2] = v.z; d[3] = v.w;
    }

    int nl = tid & 63;
    int cg = tid >> 6;
    int grow = row0 + nl;
    const float4* W4 = (const float4*)W;
    float4* Ws4 = (float4*)Ws;

    for (int chunk = 0; chunk < 3; chunk++) {
        __syncthreads();
        for (int i = tid; i < 128 * 32; i += 256) {
            int k = i >> 5, c4 = i & 31;
            Ws4[k * 32 + c4] = W4[k * 96 + chunk * 32 + c4];
        }
        __syncthreads();

        int col0 = cg * 32;
        float acc[32];
#pragma unroll
        for (int c = 0; c < 32; c++) acc[c] = 0.f;
        for (int k = 0; k < 128; k++) {
            float a = As[nl * 129 + k];
            const float4* wrow = (const float4*)(Ws + k * 128 + col0);
#pragma unroll
            for (int c4 = 0; c4 < 8; c4++) {
                float4 w = wrow[c4];
                acc[c4 * 4 + 0] = fmaf(a, w.x, acc[c4 * 4 + 0]);
                acc[c4 * 4 + 1] = fmaf(a, w.y, acc[c4 * 4 + 1]);
                acc[c4 * 4 + 2] = fmaf(a, w.z, acc[c4 * 4 + 2]);
                acc[c4 * 4 + 3] = fmaf(a, w.w, acc[c4 * 4 + 3]);
            }
        }
        if (grow < NN) {
            float* o = g_kqv + (size_t)grow * 384 + chunk * 128 + col0;
#pragma unroll
            for (int c = 0; c < 32; c++) o[c] = acc[c] + bias[chunk * 128 + col0 + c];
        }
    }
}

// ---------------- q~ = Wk[r] q[n] for every nonempty run (batched blockdiag GEMM) ----
// grid (1563, 8), block 256 = 64 entries x 4 heads. smem: WkT[h][f][d] + As[64][129]
__global__ __launch_bounds__(256) void qt_kernel(const float* __restrict__ Wk) {
    extern __shared__ float sm[];
    float* WkT = sm;            // 4096
    float* As = sm + 4096;      // 64*129
    int tid = threadIdx.x;
    int r = blockIdx.y;
    int cnt = g_lcnt[r];
    int e0 = blockIdx.x * 64;
    if (e0 >= cnt) return;

    const float* WkR = Wk + (size_t)r * 4096;   // [h][d][f]
    for (int i = tid; i < 4096; i += 256) {
        int h = i >> 10, rem = i & 1023, d = rem >> 5, f = rem & 31;
        WkT[h * 1024 + f * 32 + d] = WkR[i];
    }
    for (int i = tid; i < 64 * 32; i += 256) {
        int row = i >> 5, c4 = i & 31;
        int entry = e0 + row;
        float4 v = make_float4(0.f, 0.f, 0.f, 0.f);
        if (entry < cnt) {
            int n = g_lnode[r * NN + entry];
            v = ((const float4*)(g_kqv + (size_t)n * 384 + 128))[c4];
        }
        float* d = As + row * 129 + c4 * 4;
        d[0] = v.x; d[1] = v.y; d[2] = v.z; d[3] = v.w;
    }
    __syncthreads();

    int i = tid & 63, h = tid >> 6;
    int entry = e0 + i;
    float acc[32];
#pragma unroll
    for (int c = 0; c < 32; c++) acc[c] = 0.f;
    const float* qrow = As + i * 129 + h * 32;
    const float4* wt = (const float4*)(WkT + h * 1024);
    for (int f = 0; f < 32; f++) {
        float a = qrow[f];
        const float4* w4 = wt + f * 8;
#pragma unroll
        for (int j = 0; j < 8; j++) {
            float4 w = w4[j];
            acc[j * 4 + 0] = fmaf(a, w.x, acc[j * 4 + 0]);
            acc[j * 4 + 1] = fmaf(a, w.y, acc[j * 4 + 1]);
            acc[j * 4 + 2] = fmaf(a, w.z, acc[j * 4 + 2]);
            acc[j * 4 + 3] = fmaf(a, w.w, acc[j * 4 + 3]);
        }
    }
    if (entry < cnt) {
        float4* o = (float4*)(g_Qt + ((size_t)(r * NN + entry)) * 128 + h * 32);
#pragma unroll
        for (int j = 0; j < 8; j++)
            o[j] = make_float4(acc[j * 4], acc[j * 4 + 1], acc[j * 4 + 2], acc[j * 4 + 3]);
    }
}

// ---------------- attention: warp per dst node, per-run raw flash state ----------------
__global__ __launch_bounds__(256) void attn_kernel(const float* __restrict__ pr) {
    __shared__ float prs[RR * HH];
    if (threadIdx.x < RR * HH) prs[threadIdx.x] = pr[threadIdx.x];
    __syncthreads();
    int n = (blockIdx.x * blockDim.x + threadIdx.x) >> 5;
    int lane = threadIdx.x & 31;
    if (n >= NN) return;
    const float SCALE = 0.17677669529663689f;   // 1/sqrt(32)
    const unsigned FULL = 0xffffffffu;

    int base = n * RR;
    for (int r = 0; r < RR; r++) {
        int beg = g_off[base + r];
        int end = g_off[base + r + 1];
        if (beg == end) continue;
        int ridx = g_runidx[base + r];
        const float* qt = g_Qt + (size_t)ridx * 128;
        float qt0 = qt[lane], qt1 = qt[32 + lane], qt2 = qt[64 + lane], qt3 = qt[96 + lane];
        float pr0 = prs[r * 4 + 0] * SCALE, pr1 = prs[r * 4 + 1] * SCALE;
        float pr2 = prs[r * 4 + 2] * SCALE, pr3 = prs[r * 4 + 3] * SCALE;

        float rm0 = -INFINITY, rm1 = -INFINITY, rm2 = -INFINITY, rm3 = -INFINITY;
        float rd0 = 0.f, rd1 = 0.f, rd2 = 0.f, rd3 = 0.f;
        float ra0 = 0.f, ra1 = 0.f, ra2 = 0.f, ra3 = 0.f;

        for (int e = beg; e < end; e++) {
            int src = g_esrc[e];
            const float* kb = g_kqv + (size_t)src * 384;
            float k0 = kb[lane], k1 = kb[32 + lane], k2 = kb[64 + lane], k3 = kb[96 + lane];
            float v0 = kb[256 + lane], v1 = kb[288 + lane], v2 = kb[320 + lane], v3 = kb[352 + lane];
            float p0 = k0 * qt0, p1 = k1 * qt1, p2 = k2 * qt2, p3 = k3 * qt3;
#pragma unroll
            for (int off = 16; off > 0; off >>= 1) {
                p0 += __shfl_xor_sync(FULL, p0, off);
                p1 += __shfl_xor_sync(FULL, p1, off);
                p2 += __shfl_xor_sync(FULL, p2, off);
                p3 += __shfl_xor_sync(FULL, p3, off);
            }
            float s0 = p0 * pr0, s1 = p1 * pr1, s2 = p2 * pr2, s3 = p3 * pr3;
            float nm, c, w;
            nm = fmaxf(rm0, s0); c = __expf(rm0 - nm); w = __expf(s0 - nm);
            rd0 = rd0 * c + w; ra0 = ra0 * c + w * v0; rm0 = nm;
            nm = fmaxf(rm1, s1); c = __expf(rm1 - nm); w = __expf(s1 - nm);
            rd1 = rd1 * c + w; ra1 = ra1 * c + w * v1; rm1 = nm;
            nm = fmaxf(rm2, s2); c = __expf(rm2 - nm); w = __expf(s2 - nm);
            rd2 = rd2 * c + w; ra2 = ra2 * c + w * v2; rm2 = nm;
            nm = fmaxf(rm3, s3); c = __expf(rm3 - nm); w = __expf(s3 - nm);
            rd3 = rd3 * c + w; ra3 = ra3 * c + w * v3; rm3 = nm;
        }

        if (lane == 0) {
            g_rm[(size_t)ridx * 4 + 0] = rm0; g_rm[(size_t)ridx * 4 + 1] = rm1;
            g_rm[(size_t)ridx * 4 + 2] = rm2; g_rm[(size_t)ridx * 4 + 3] = rm3;
            g_rd[(size_t)ridx * 4 + 0] = rd0; g_rd[(size_t)ridx * 4 + 1] = rd1;
            g_rd[(size_t)ridx * 4 + 2] = rd2; g_rd[(size_t)ridx * 4 + 3] = rd3;
        }
        float* vr = g_Vr + (size_t)ridx * 128;
        vr[lane] = ra0; vr[32 + lane] = ra1; vr[64 + lane] = ra2; vr[96 + lane] = ra3;
    }
}

// ---------------- apply Wv[r] to raw per-run v-sums in place ----------------
__global__ __launch_bounds__(256) void vt_kernel(const float* __restrict__ Wv) {
    extern __shared__ float sm[];
    float* WvS = sm;            // 4096 : [h][d][f]
    float* As = sm + 4096;      // 64*129
    int tid = threadIdx.x;
    int r = blockIdx.y;
    int cnt = g_lcnt[r];
    int e0 = blockIdx.x * 64;
    if (e0 >= cnt) return;

    const float* WvR = Wv + (size_t)r * 4096;
    for (int i = tid; i < 4096; i += 256) WvS[i] = WvR[i];
    for (int i = tid; i < 64 * 32; i += 256) {
        int row = i >> 5, c4 = i & 31;
        int entry = e0 + row;
        float4 v = make_float4(0.f, 0.f, 0.f, 0.f);
        if (entry < cnt)
            v = ((const float4*)(g_Vr + ((size_t)(r * NN + entry)) * 128))[c4];
        float* d = As + row * 129 + c4 * 4;
        d[0] = v.x; d[1] = v.y; d[2] = v.z; d[3] = v.w;
    }
    __syncthreads();

    int i = tid & 63, h = tid >> 6;
    int entry = e0 + i;
    float acc[32];
#pragma unroll
    for (int c = 0; c < 32; c++) acc[c] = 0.f;
    const float* arow = As + i * 129 + h * 32;
    const float4* wv = (const float4*)(WvS + h * 1024);
    for (int d = 0; d < 32; d++) {
        float a = arow[d];
        const float4* w4 = wv + d * 8;
#pragma unroll
        for (int j = 0; j < 8; j++) {
            float4 w = w4[j];
            acc[j * 4 + 0] = fmaf(a, w.x, acc[j * 4 + 0]);
            acc[j * 4 + 1] = fmaf(a, w.y, acc[j * 4 + 1]);
            acc[j * 4 + 2] = fmaf(a, w.z, acc[j * 4 + 2]);
            acc[j * 4 + 3] = fmaf(a, w.w, acc[j * 4 + 3]);
        }
    }
    if (entry < cnt) {
        float4* o = (float4*)(g_Vr + ((size_t)(r * NN + entry)) * 128 + h * 32);
#pragma unroll
        for (int j = 0; j < 8; j++)
            o[j] = make_float4(acc[j * 4], acc[j * 4 + 1], acc[j * 4 + 2], acc[j * 4 + 3]);
    }
}

// ---------------- merge runs per node, finalize softmax ----------------
__global__ __launch_bounds__(256) void merge_kernel() {
    int n = (blockIdx.x * blockDim.x + threadIdx.x) >> 5;
    int lane = threadIdx.x & 31;
    if (n >= NN) return;

    float M0 = -INFINITY, M1 = -INFINITY, M2 = -INFINITY, M3 = -INFINITY;
    float D0 = 0.f, D1 = 0.f, D2 = 0.f, D3 = 0.f;
    float O0 = 0.f, O1 = 0.f, O2 = 0.f, O3 = 0.f;

    int base = n * RR;
    for (int r = 0; r < RR; r++) {
        int ridx = g_runidx[base + r];
        if (ridx < 0) continue;
        float m0 = g_rm[(size_t)ridx * 4 + 0], m1 = g_rm[(size_t)ridx * 4 + 1];
        float m2 = g_rm[(size_t)ridx * 4 + 2], m3 = g_rm[(size_t)ridx * 4 + 3];
        float d0 = g_rd[(size_t)ridx * 4 + 0], d1 = g_rd[(size_t)ridx * 4 + 1];
        float d2 = g_rd[(size_t)ridx * 4 + 2], d3 = g_rd[(size_t)ridx * 4 + 3];
        const float* vr = g_Vr + (size_t)ridx * 128;
        float v0 = vr[lane], v1 = vr[32 + lane], v2 = vr[64 + lane], v3 = vr[96 + lane];

        float nm, c1, c2;
        nm = fmaxf(M0, m0); c1 = __expf(M0 - nm); c2 = __expf(m0 - nm);
        D0 = D0 * c1 + d0 * c2; O0 = O0 * c1 + v0 * c2; M0 = nm;
        nm = fmaxf(M1, m1); c1 = __expf(M1 - nm); c2 = __expf(m1 - nm);
        D1 = D1 * c1 + d1 * c2; O1 = O1 * c1 + v1 * c2; M1 = nm;
        nm = fmaxf(M2, m2); c1 = __expf(M2 - nm); c2 = __expf(m2 - nm);
        D2 = D2 * c1 + d2 * c2; O2 = O2 * c1 + v2 * c2; M2 = nm;
        nm = fmaxf(M3, m3); c1 = __expf(M3 - nm); c2 = __expf(m3 - nm);
        D3 = D3 * c1 + d3 * c2; O3 = O3 * c1 + v3 * c2; M3 = nm;
    }
    float* og = g_aggr + (size_t)n * 128;
    og[lane]      = (D0 > 0.f) ? O0 / D0 : 0.f;
    og[32 + lane] = (D1 > 0.f) ? O1 / D1 : 0.f;
    og[64 + lane] = (D2 > 0.f) ? O2 / D2 : 0.f;
    og[96 + lane] = (D3 > 0.f) ? O3 / D3 : 0.f;
}

// ---------------- out: o = gelu(aggr) @ W_out + b; h = relu(sg*o + (1-sg)*h) ----------------
__global__ __launch_bounds__(256) void out_gemm_kernel(const float* __restrict__ W,
                                                       const float* __restrict__ bias,
                                                       const float* __restrict__ skip,
                                                       int l, float* __restrict__ out2) {
    extern __shared__ float sm[];
    float* Ws = sm;                // 128*128
    float* As = sm + 128 * 128;    // 64*129
    int tid = threadIdx.x;
    int row0 = blockIdx.x * TILE_M;

    const float4* W4 = (const float4*)W;
    float4* Ws4 = (float4*)Ws;
    for (int i = tid; i < 128 * 128 / 4; i += 256) Ws4[i] = W4[i];
    for (int i = tid; i < TILE_M * 32; i += 256) {
        int row = i >> 5, c4 = i & 31;
        int gr = row0 + row;
        float4 v = (gr < NN) ? ((const float4*)(g_aggr + (size_t)gr * 128))[c4]
                             : make_float4(0.f, 0.f, 0.f, 0.f);
        float* d = As + row * 129 + c4 * 4;
        d[0] = 0.5f * v.x * (1.f + erff(v.x * 0.70710678118654752f));
        d[1] = 0.5f * v.y * (1.f + erff(v.y * 0.70710678118654752f));
        d[2] = 0.5f * v.z * (1.f + erff(v.z * 0.70710678118654752f));
        d[3] = 0.5f * v.w * (1.f + erff(v.w * 0.70710678118654752f));
    }
    __syncthreads();

    int nl = tid & 63;
    int cg = tid >> 6;
    int grow = row0 + nl;
    int col0 = cg * 32;
    float acc[32];
#pragma unroll
    for (int c = 0; c < 32; c++) acc[c] = 0.f;
    for (int k = 0; k < 128; k++) {
        float a = As[nl * 129 + k];
        const float4* wrow = (const float4*)(Ws + k * 128 + col0);
#pragma unroll
        for (int c4 = 0; c4 < 8; c4++) {
            float4 w = wrow[c4];
            acc[c4 * 4 + 0] = fmaf(a, w.x, acc[c4 * 4 + 0]);
            acc[c4 * 4 + 1] = fmaf(a, w.y, acc[c4 * 4 + 1]);
            acc[c4 * 4 + 2] = fmaf(a, w.z, acc[c4 * 4 + 2]);
            acc[c4 * 4 + 3] = fmaf(a, w.w, acc[c4 * 4 + 3]);
        }
    }
    if (grow < NN) {
        float sg = 1.f / (1.f + expf(-skip[l]));
        float* hrow = g_h + (size_t)grow * 128 + col0;
#pragma unroll
        for (int c = 0; c < 32; c++) {
            float o = acc[c] + bias[col0 + c];
            float hn = fmaxf(sg * o + (1.f - sg) * hrow[c], 0.f);
            hrow[c] = hn;
            if (out2) out2[(size_t)grow * 128 + col0 + c] = hn;
        }
    }
}

// ---------------- host ----------------
extern "C" void kernel_launch(void* const* d_in, const int* in_sizes, int n_in,
                              void* d_out, int out_size) {
    const float* emb   = (const float*)d_in[0];
    const float* W_kqv = (const float*)d_in[1];
    const float* b_kqv = (const float*)d_in[2];
    const float* Wk    = (const float*)d_in[3];
    const float* Wv    = (const float*)d_in[4];
    const float* p_rel = (const float*)d_in[5];
    const float* W_out = (const float*)d_in[6];
    const float* b_out = (const float*)d_in[7];
    const float* skip  = (const float*)d_in[8];
    const int*   x     = (const int*)d_in[9];
    const int*   ei    = (const int*)d_in[10];
    const int*   et    = (const int*)d_in[11];
    float* out = (float*)d_out;

    const int SMEM_GEMM = (128 * 128 + 64 * 129) * 4;    // 98560
    const int SMEM_QT   = (4096 + 64 * 129) * 4;         // 49408
    static bool attr_set = false;
    if (!attr_set) {
        cudaFuncSetAttribute(kqv_gemm_kernel, cudaFuncAttributeMaxDynamicSharedMemorySize, SMEM_GEMM);
        cudaFuncSetAttribute(out_gemm_kernel, cudaFuncAttributeMaxDynamicSharedMemorySize, SMEM_GEMM);
        cudaFuncSetAttribute(qt_kernel, cudaFuncAttributeMaxDynamicSharedMemorySize, SMEM_QT);
        cudaFuncSetAttribute(vt_kernel, cudaFuncAttributeMaxDynamicSharedMemorySize, SMEM_QT);
        attr_set = true;
    }

    const int nblocks_nh = (NN * HID + 255) / 256;
    const int nblocks_m  = (NN + TILE_M - 1) / TILE_M;   // 1563
    const int nblocks_e  = (EE + 255) / 256;
    const int nblocks_kb = (KB + 255) / 256;
    const int nblocks_kb1 = (KB + 1 + 255) / 256;
    const int nblocks_w  = (NN * 32 + 255) / 256;        // warp per node: 12500

    gather_kernel<<<nblocks_nh, 256>>>(emb, x);

    // sort edges by (dst, rel) into CSR + compact run lists
    zero_deg_kernel<<<nblocks_kb, 256>>>();
    hist_kernel<<<nblocks_e, 256>>>(ei, et);
    scan1_kernel<<<NB2, 1024>>>();
    scan2_kernel<<<1, 1024>>>();
    scan3_kernel<<<nblocks_kb1, 256>>>();
    scatter_kernel<<<nblocks_e, 256>>>(ei, et);
    build_lists_kernel<<<nblocks_kb, 256>>>();

    dim3 tg(nblocks_m, RR);
    for (int l = 0; l < LL; l++) {
        const float* Wkqv_l = W_kqv + (size_t)l * HID * 3 * HID;
        const float* bkqv_l = b_kqv + (size_t)l * 3 * HID;
        const float* Wk_l   = Wk + (size_t)l * RR * HH * DD * DD;
        const float* Wv_l   = Wv + (size_t)l * RR * HH * DD * DD;
        const float* pr_l   = p_rel + (size_t)l * RR * HH;
        const float* Wout_l = W_out + (size_t)l * HID * HID;
        const float* bout_l = b_out + (size_t)l * HID;

        kqv_gemm_kernel<<<nblocks_m, 256, SMEM_GEMM>>>(Wkqv_l, bkqv_l);
        qt_kernel<<<tg, 256, SMEM_QT>>>(Wk_l);
        attn_kernel<<<nblocks_w, 256>>>(pr_l);
        vt_kernel<<<tg, 256, SMEM_QT>>>(Wv_l);
        merge_kernel<<<nblocks_w, 256>>>();
        out_gemm_kernel<<<nblocks_m, 256, SMEM_GEMM>>>(Wout_l, bout_l, skip, l,
                                                       (l == LL - 1) ? out : nullptr);
    }
}